// round 2
// baseline (speedup 1.0000x reference)
#include <cuda_runtime.h>
#include <cuda_bf16.h>

// GaussianConditionalStanh: fused quantize(symbols) + dequantize.
//   y = inputs - means
//   idx = searchsorted(mid, y)  where mid = 0.5*(c[l]+c[l+1]), side='left'
//   symbols = idx (written as float32 into out[0:N])
//   dequant = codebook[idx] + means (written into out[N:2N])
//
// Strategy: streaming kernel, float4-vectorized, branchless binary search
// over 59 midpoints held in shared memory. Memory-bound: 16 B/elem.

#define L_CODE 60
#define NMID   59

__global__ __launch_bounds__(256)
void gcs_kernel(const float4* __restrict__ x4,
                const float4* __restrict__ m4,
                const float*  __restrict__ codebook,
                float4* __restrict__ sym4,
                float4* __restrict__ dq4,
                int n4)
{
    __shared__ float sc[L_CODE];     // codebook
    __shared__ float smid[NMID + 1]; // midpoints (+pad)

    // Cooperative load of codebook + midpoint computation (tiny).
    if (threadIdx.x < L_CODE) {
        float c = codebook[threadIdx.x];
        sc[threadIdx.x] = c;
    }
    __syncthreads();
    if (threadIdx.x < NMID) {
        smid[threadIdx.x] = 0.5f * (sc[threadIdx.x] + sc[threadIdx.x + 1]);
    }
    __syncthreads();

    int i = blockIdx.x * blockDim.x + threadIdx.x;
    int stride = gridDim.x * blockDim.x;

    for (; i < n4; i += stride) {
        float4 xv = x4[i];
        float4 mv = m4[i];

        float y0 = xv.x - mv.x;
        float y1 = xv.y - mv.y;
        float y2 = xv.z - mv.z;
        float y3 = xv.w - mv.w;

        // Branchless binary search: idx = count of (mid < y), idx in [0, 59].
        // Invariant: largest idx such that mid[idx-1] < y.
        int i0 = 0, i1 = 0, i2 = 0, i3 = 0;
        #pragma unroll
        for (int step = 32; step > 0; step >>= 1) {
            int n0 = i0 + step; if (n0 <= NMID && smid[n0 - 1] < y0) i0 = n0;
            int n1 = i1 + step; if (n1 <= NMID && smid[n1 - 1] < y1) i1 = n1;
            int n2 = i2 + step; if (n2 <= NMID && smid[n2 - 1] < y2) i2 = n2;
            int n3 = i3 + step; if (n3 <= NMID && smid[n3 - 1] < y3) i3 = n3;
        }

        float4 sv;
        sv.x = (float)i0; sv.y = (float)i1; sv.z = (float)i2; sv.w = (float)i3;
        sym4[i] = sv;

        float4 dv;
        dv.x = sc[i0] + mv.x;
        dv.y = sc[i1] + mv.y;
        dv.z = sc[i2] + mv.z;
        dv.w = sc[i3] + mv.w;
        dq4[i] = dv;
    }
}

extern "C" void kernel_launch(void* const* d_in, const int* in_sizes, int n_in,
                              void* d_out, int out_size)
{
    const float* inputs   = (const float*)d_in[0];
    const float* means    = (const float*)d_in[1];
    const float* codebook = (const float*)d_in[2];
    float* out = (float*)d_out;

    int n  = in_sizes[0];      // 28,311,552 (divisible by 4)
    int n4 = n / 4;

    float* sym = out;          // symbols as float32, first n elements
    float* dq  = out + n;      // dequantized values, next n elements

    const int threads = 256;
    int blocks = (n4 + threads - 1) / threads;

    gcs_kernel<<<blocks, threads>>>(
        (const float4*)inputs, (const float4*)means, codebook,
        (float4*)sym, (float4*)dq, n4);
}